// round 6
// baseline (speedup 1.0000x reference)
#include <cuda_runtime.h>
#include <math.h>
#include <stdint.h>

// Problem shapes (fixed)
#define S_LEN 1024
#define HEADS 8
#define DH    64
#define BM    64
#define BN    64
#define KSTR  68   // K smem row stride (floats): 272B = 16B-aligned, conflict-free
#define VSTR  72   // V smem row stride (floats): 288B = 16B-aligned, conflict-free

// Bias lookup tables
#define NTAB   2048
#define TAB_LO (-0.5f)
#define TAB_HI (10.5f)

__device__ float2 g_tab[2][NTAB];

__device__ __forceinline__ float gelu_exact(float x) {
    return 0.5f * x * (1.0f + erff(x * 0.70710678118654752f));
}

// ---------------------------------------------------------------------------
// Kernel 1: build the two scalar-bias tables (negligible cost, accurate math)
// ---------------------------------------------------------------------------
__global__ void build_tables_kernel(
    const float* __restrict__ muD, const float* __restrict__ sgD, const float* __restrict__ bD,
    const float* __restrict__ muE, const float* __restrict__ sgE, const float* __restrict__ bE,
    const float* __restrict__ W1,  const float* __restrict__ b1,
    const float* __restrict__ W2,  const float* __restrict__ b2,
    int KG)
{
    int t     = blockIdx.x * blockDim.x + threadIdx.x;
    int which = blockIdx.y;
    if (t >= NTAB) return;

    const float* mu = which ? muE : muD;
    const float* sg = which ? sgE : sgD;
    const float* bb = which ? bE  : bD;

    const float step = (TAB_HI - TAB_LO) / (float)NTAB;

    float f[2];
    #pragma unroll
    for (int p = 0; p < 2; ++p) {
        float x = TAB_LO + (float)(t + p) * step;
        float psi[16];
        for (int k = 0; k < KG; ++k) {
            float s  = sg[k];
            float z  = (x + bb[k] - mu[k]) / s;
            float in = 0.3989422804014327f / s;
            psi[k]   = expf(-0.5f * z * z) * in;
        }
        float hv[16];
        for (int l = 0; l < KG; ++l) {
            float acc = b1[l];
            for (int k = 0; k < KG; ++k) acc += psi[k] * W1[l * KG + k];
            hv[l] = gelu_exact(acc);
        }
        float o = b2[0];
        for (int l = 0; l < KG; ++l) o += hv[l] * W2[l];
        f[p] = o;
    }
    g_tab[which][t] = make_float2(f[0], f[1] - f[0]);
}

// ---------------------------------------------------------------------------
// helpers
// ---------------------------------------------------------------------------
__device__ __forceinline__ uint32_t f2tf(float x) {
    uint32_t u;
    asm("cvt.rna.tf32.f32 %0, %1;" : "=r"(u) : "f"(x));
    return u;
}

__device__ __forceinline__ void mma_tf32(
    float& c0, float& c1, float& c2, float& c3,
    uint32_t a0, uint32_t a1, uint32_t a2, uint32_t a3,
    uint32_t b0, uint32_t b1)
{
    asm volatile(
        "mma.sync.aligned.m16n8k8.row.col.f32.tf32.tf32.f32 "
        "{%0,%1,%2,%3}, {%4,%5,%6,%7}, {%8,%9}, {%0,%1,%2,%3};"
        : "+f"(c0), "+f"(c1), "+f"(c2), "+f"(c3)
        : "r"(a0), "r"(a1), "r"(a2), "r"(a3), "r"(b0), "r"(b1));
}

__device__ __forceinline__ void cp_async16(uint32_t dst, const void* src) {
    asm volatile("cp.async.cg.shared.global [%0], [%1], 16;"
                 :: "r"(dst), "l"(src));
}
__device__ __forceinline__ void cp_commit() {
    asm volatile("cp.async.commit_group;");
}
template <int N>
__device__ __forceinline__ void cp_wait() {
    asm volatile("cp.async.wait_group %0;" :: "n"(N));
}

__device__ __forceinline__ float lut(const float2* __restrict__ t, float x, float inv_step) {
    float tt = (x - TAB_LO) * inv_step;
    int ix = (int)tt;
    ix = min(max(ix, 0), NTAB - 1);
    float fr = tt - (float)ix;
    float2 e = t[ix];
    return fmaf(fr, e.y, e.x);
}

// ---------------------------------------------------------------------------
// Kernel 2: fused flash attention, tf32 tensor cores, cp.async-pipelined.
// Grid (16, 8), 256 threads = 8 warps: 4 m-stripes (16 rows) x 2 key-halves.
// ---------------------------------------------------------------------------
__global__ void __launch_bounds__(256, 1)
attn_kernel(const float* __restrict__ Q, const float* __restrict__ K,
            const float* __restrict__ V,
            const float* __restrict__ dist, const float* __restrict__ ener,
            const int*   __restrict__ mask,
            float* __restrict__ out)
{
    extern __shared__ float sm[];
    float*  Kb0  = sm;                        // [2] x 64 x KSTR (raw f32)
    float*  Kb1  = Kb0 + 64 * KSTR;
    float*  Vb0  = Kb1 + 64 * KSTR;           // [2] x 64 x VSTR (raw f32)
    float*  Vb1  = Vb0 + 64 * VSTR;
    float*  Mred = Vb1 + 64 * VSTR;           // [2][64]
    float*  Lred = Mred + 128;                // [2][64]
    float2* tD   = (float2*)(Lred + 128);     // NTAB
    float2* tE   = tD + NTAB;                 // NTAB

    const int tid  = threadIdx.x;
    const int w    = tid >> 5;
    const int lane = tid & 31;
    const int g    = lane >> 2;
    const int qd   = lane & 3;
    const int mw   = w >> 1;
    const int half = w & 1;
    const int r_lo = mw * 16 + g;
    const int r_hi = r_lo + 8;
    const int nbase = half * 32;
    const int h    = blockIdx.y;
    const int q0   = blockIdx.x * BM;

    // per-thread copy slots: 4 float4s of K, 4 of V per tile
    const int cr  = tid >> 4;          // row 0..15 base (x4 rows via +16 step)
    const int cc4 = (tid & 15) << 2;   // col (float)

    const float* Kg0 = K + (size_t)h * S_LEN * DH;
    const float* Vg0 = V + (size_t)h * S_LEN * DH;

    uint32_t kdst[2][4], vdst[2][4];
    #pragma unroll
    for (int b = 0; b < 2; ++b) {
        float* kb = b ? Kb1 : Kb0;
        float* vb = b ? Vb1 : Vb0;
        #pragma unroll
        for (int p = 0; p < 4; ++p) {
            int r = cr + p * 16;
            kdst[b][p] = (uint32_t)__cvta_generic_to_shared(&kb[r * KSTR + cc4]);
            vdst[b][p] = (uint32_t)__cvta_generic_to_shared(&vb[r * VSTR + cc4]);
        }
    }

    // ---- stage tables ----
    for (int i = tid; i < NTAB; i += 256) {
        tD[i] = g_tab[0][i];
        tE[i] = g_tab[1][i];
    }

    // ---- prologue: issue K/V tile 0 copy ----
    {
        const float* Kg = Kg0;
        const float* Vg = Vg0;
        #pragma unroll
        for (int p = 0; p < 4; ++p) {
            int r = cr + p * 16;
            cp_async16(kdst[0][p], Kg + r * DH + cc4);
            cp_async16(vdst[0][p], Vg + r * DH + cc4);
        }
        cp_commit();
    }

    // ---- Q fragments -> registers (tf32-rounded, pre-scaled) ----
    const float SCALE = 0.08838834764831845f;   // 1/sqrt(2*D)
    const float* Qg = Q + ((size_t)h * S_LEN + q0) * DH;
    uint32_t qf[8][4];
    #pragma unroll
    for (int kf = 0; kf < 8; ++kf) {
        int k0 = kf * 8;
        qf[kf][0] = f2tf(Qg[r_lo * DH + k0 + qd]     * SCALE);
        qf[kf][1] = f2tf(Qg[r_hi * DH + k0 + qd]     * SCALE);
        qf[kf][2] = f2tf(Qg[r_lo * DH + k0 + qd + 4] * SCALE);
        qf[kf][3] = f2tf(Qg[r_hi * DH + k0 + qd + 4] * SCALE);
    }

    float o[8][4];
    #pragma unroll
    for (int j = 0; j < 8; ++j)
        #pragma unroll
        for (int c = 0; c < 4; ++c) o[j][c] = 0.f;

    float m_lo = -1e30f, m_hi = -1e30f, l_lo = 0.f, l_hi = 0.f;
    const float inv_step = (float)NTAB / (TAB_HI - TAB_LO);

    for (int jt = 0; jt < S_LEN / BN; ++jt) {
        const int buf = jt & 1;
        const float* Ksb = buf ? Kb1 : Kb0;
        const float* Vsb = buf ? Vb1 : Vb0;

        // ---- issue next tile's K/V copy into the other buffer ----
        if (jt + 1 < S_LEN / BN) {
            const float* Kg = Kg0 + (size_t)(jt + 1) * BN * DH;
            const float* Vg = Vg0 + (size_t)(jt + 1) * BN * DH;
            #pragma unroll
            for (int p = 0; p < 4; ++p) {
                int r = cr + p * 16;
                cp_async16(kdst[buf ^ 1][p], Kg + r * DH + cc4);
                cp_async16(vdst[buf ^ 1][p], Vg + r * DH + cc4);
            }
            cp_commit();
        }

        // ---- issue bias-stream loads for THIS tile (land during QK mma) ----
        size_t base_lo = ((size_t)h * S_LEN + q0 + r_lo) * S_LEN
                         + (size_t)(jt * BN + nbase + 2 * qd);
        size_t base_hi = base_lo + (size_t)8 * S_LEN;

        float2 dlo[4], dhi[4], elo[4], ehi[4];
        int2   mlo[4], mhi[4];
        #pragma unroll
        for (int j = 0; j < 4; ++j) {
            dlo[j] = *(const float2*)(dist + base_lo + j * 8);
            dhi[j] = *(const float2*)(dist + base_hi + j * 8);
            elo[j] = *(const float2*)(ener + base_lo + j * 8);
            ehi[j] = *(const float2*)(ener + base_hi + j * 8);
            mlo[j] = *(const int2*)(mask + base_lo + j * 8);
            mhi[j] = *(const int2*)(mask + base_hi + j * 8);
        }

        // ---- wait for THIS tile's K/V (leave next tile's group in flight) ----
        if (jt + 1 < S_LEN / BN) cp_wait<1>(); else cp_wait<0>();
        __syncthreads();

        // ---- S = Q K^T : warp computes m16 x n32 ----
        float s[4][4];
        #pragma unroll
        for (int j = 0; j < 4; ++j)
            #pragma unroll
            for (int c = 0; c < 4; ++c) s[j][c] = 0.f;

        #pragma unroll
        for (int kf = 0; kf < 8; ++kf) {
            #pragma unroll
            for (int j = 0; j < 4; ++j) {
                int key = nbase + j * 8 + g;
                uint32_t b0 = f2tf(Ksb[key * KSTR + kf * 8 + qd]);
                uint32_t b1 = f2tf(Ksb[key * KSTR + kf * 8 + qd + 4]);
                mma_tf32(s[j][0], s[j][1], s[j][2], s[j][3],
                         qf[kf][0], qf[kf][1], qf[kf][2], qf[kf][3], b0, b1);
            }
        }

        // ---- apply biases + mask (data already in registers) ----
        #pragma unroll
        for (int j = 0; j < 4; ++j) {
            float v00 = s[j][0] + lut(tD, dlo[j].x, inv_step) + lut(tE, elo[j].x, inv_step);
            float v01 = s[j][1] + lut(tD, dlo[j].y, inv_step) + lut(tE, elo[j].y, inv_step);
            float v10 = s[j][2] + lut(tD, dhi[j].x, inv_step) + lut(tE, ehi[j].x, inv_step);
            float v11 = s[j][3] + lut(tD, dhi[j].y, inv_step) + lut(tE, ehi[j].y, inv_step);
            s[j][0] = (mlo[j].x == 0) ? -1e9f : v00;
            s[j][1] = (mlo[j].y == 0) ? -1e9f : v01;
            s[j][2] = (mhi[j].x == 0) ? -1e9f : v10;
            s[j][3] = (mhi[j].y == 0) ? -1e9f : v11;
        }

        // ---- online softmax ----
        float pl = -1e30f, ph = -1e30f;
        #pragma unroll
        for (int j = 0; j < 4; ++j) {
            pl = fmaxf(pl, fmaxf(s[j][0], s[j][1]));
            ph = fmaxf(ph, fmaxf(s[j][2], s[j][3]));
        }
        pl = fmaxf(pl, __shfl_xor_sync(0xffffffffu, pl, 1));
        pl = fmaxf(pl, __shfl_xor_sync(0xffffffffu, pl, 2));
        ph = fmaxf(ph, __shfl_xor_sync(0xffffffffu, ph, 1));
        ph = fmaxf(ph, __shfl_xor_sync(0xffffffffu, ph, 2));
        if (qd == 0) {
            Mred[half * 64 + r_lo] = pl;
            Mred[half * 64 + r_hi] = ph;
        }
        __syncthreads();
        float nm_lo = fmaxf(m_lo, fmaxf(Mred[r_lo], Mred[64 + r_lo]));
        float nm_hi = fmaxf(m_hi, fmaxf(Mred[r_hi], Mred[64 + r_hi]));
        float c_lo = __expf(m_lo - nm_lo);
        float c_hi = __expf(m_hi - nm_hi);
        m_lo = nm_lo; m_hi = nm_hi;

        float sl = 0.f, sh = 0.f;
        #pragma unroll
        for (int j = 0; j < 4; ++j) {
            s[j][0] = __expf(s[j][0] - nm_lo); sl += s[j][0];
            s[j][1] = __expf(s[j][1] - nm_lo); sl += s[j][1];
            s[j][2] = __expf(s[j][2] - nm_hi); sh += s[j][2];
            s[j][3] = __expf(s[j][3] - nm_hi); sh += s[j][3];
        }
        sl += __shfl_xor_sync(0xffffffffu, sl, 1);
        sl += __shfl_xor_sync(0xffffffffu, sl, 2);
        sh += __shfl_xor_sync(0xffffffffu, sh, 1);
        sh += __shfl_xor_sync(0xffffffffu, sh, 2);
        l_lo = l_lo * c_lo + sl;
        l_hi = l_hi * c_hi + sh;

        #pragma unroll
        for (int j = 0; j < 8; ++j) {
            o[j][0] *= c_lo; o[j][1] *= c_lo;
            o[j][2] *= c_hi; o[j][3] *= c_hi;
        }

        // ---- O += P V : shfl P (C-layout) into A-layout tf32 fragments ----
        const int kb = half * 32;
        const int l0 = g * 4 + (qd >> 1);
        const int l1 = l0 + 2;
        const bool odd = (qd & 1);
        #pragma unroll
        for (int kf = 0; kf < 4; ++kf) {
            float v0 = __shfl_sync(0xffffffffu, s[kf][0], l0);
            float v1 = __shfl_sync(0xffffffffu, s[kf][1], l0);
            float v2 = __shfl_sync(0xffffffffu, s[kf][2], l0);
            float v3 = __shfl_sync(0xffffffffu, s[kf][3], l0);
            float w0 = __shfl_sync(0xffffffffu, s[kf][0], l1);
            float w1 = __shfl_sync(0xffffffffu, s[kf][1], l1);
            float w2 = __shfl_sync(0xffffffffu, s[kf][2], l1);
            float w3 = __shfl_sync(0xffffffffu, s[kf][3], l1);
            uint32_t a0 = f2tf(odd ? v1 : v0);
            uint32_t a1 = f2tf(odd ? v3 : v2);
            uint32_t a2 = f2tf(odd ? w1 : w0);
            uint32_t a3 = f2tf(odd ? w3 : w2);
            int vr = kb + kf * 8 + qd;
            #pragma unroll
            for (int j = 0; j < 8; ++j) {
                uint32_t b0 = f2tf(Vsb[vr * VSTR + j * 8 + g]);
                uint32_t b1 = f2tf(Vsb[(vr + 4) * VSTR + j * 8 + g]);
                mma_tf32(o[j][0], o[j][1], o[j][2], o[j][3], a0, a1, a2, a3, b0, b1);
            }
        }
        __syncthreads();   // all reads of this buffer done before it's refilled
    }

    // ---- epilogue: combine the two key-halves, normalize, store ----
    if (qd == 0) {
        Lred[half * 64 + r_lo] = l_lo;
        Lred[half * 64 + r_hi] = l_hi;
    }
    float* Obuf = Kb0;   // safe: trailing loop sync drained all reads
    if (half == 0) {
        #pragma unroll
        for (int j = 0; j < 8; ++j) {
            *(float2*)&Obuf[r_lo * KSTR + j * 8 + 2 * qd] = make_float2(o[j][0], o[j][1]);
            *(float2*)&Obuf[r_hi * KSTR + j * 8 + 2 * qd] = make_float2(o[j][2], o[j][3]);
        }
    }
    __syncthreads();
    if (half == 1) {
        float il_lo = 1.0f / (Lred[r_lo] + Lred[64 + r_lo]);
        float il_hi = 1.0f / (Lred[r_hi] + Lred[64 + r_hi]);
        float* og = out + ((size_t)h * S_LEN + q0) * DH;
        #pragma unroll
        for (int j = 0; j < 8; ++j) {
            float2 t0 = *(float2*)&Obuf[r_lo * KSTR + j * 8 + 2 * qd];
            float2 t1 = *(float2*)&Obuf[r_hi * KSTR + j * 8 + 2 * qd];
            float2 r0 = make_float2((o[j][0] + t0.x) * il_lo, (o[j][1] + t0.y) * il_lo);
            float2 r1 = make_float2((o[j][2] + t1.x) * il_hi, (o[j][3] + t1.y) * il_hi);
            *(float2*)(og + r_lo * DH + j * 8 + 2 * qd) = r0;
            *(float2*)(og + r_hi * DH + j * 8 + 2 * qd) = r1;
        }
    }
}

// ---------------------------------------------------------------------------
// Launch
// ---------------------------------------------------------------------------
extern "C" void kernel_launch(void* const* d_in, const int* in_sizes, int n_in,
                              void* d_out, int out_size)
{
    const float* Q    = (const float*)d_in[0];
    const float* K    = (const float*)d_in[1];
    const float* V    = (const float*)d_in[2];
    const float* dist = (const float*)d_in[3];
    const float* ener = (const float*)d_in[4];
    const int*   mask = (const int*)  d_in[5];
    const float* muD  = (const float*)d_in[6];
    const float* sgD  = (const float*)d_in[7];
    const float* bD   = (const float*)d_in[8];
    const float* muE  = (const float*)d_in[9];
    const float* sgE  = (const float*)d_in[10];
    const float* bE   = (const float*)d_in[11];
    const float* W1   = (const float*)d_in[12];
    const float* b1   = (const float*)d_in[13];
    const float* W2   = (const float*)d_in[14];
    const float* b2   = (const float*)d_in[15];
    float* out = (float*)d_out;

    int KG = in_sizes[6];
    if (KG > 16) KG = 16;

    build_tables_kernel<<<dim3(NTAB / 256, 2), 256>>>(
        muD, sgD, bD, muE, sgE, bE, W1, b1, W2, b2, KG);

    const int SMEM_BYTES = (2 * 64 * KSTR + 2 * 64 * VSTR + 256) * (int)sizeof(float)
                         + 2 * NTAB * (int)sizeof(float2);
    cudaFuncSetAttribute(attn_kernel,
                         cudaFuncAttributeMaxDynamicSharedMemorySize, SMEM_BYTES);

    attn_kernel<<<dim3(S_LEN / BM, HEADS), 256, SMEM_BYTES>>>(
        Q, K, V, dist, ener, mask, out);
}

// round 7
// speedup vs baseline: 1.5000x; 1.5000x over previous
#include <cuda_runtime.h>
#include <math.h>
#include <stdint.h>

// Problem shapes (fixed)
#define S_LEN 1024
#define HEADS 8
#define DH    64
#define BM    64
#define BN    64
#define KSTR  68
#define VSTR  72
#define NTHREADS 512

// Bias lookup tables
#define NTAB   2048
#define TAB_LO (-0.5f)
#define TAB_HI (10.5f)

__device__ float2 g_tab[2][NTAB];

__device__ __forceinline__ float gelu_exact(float x) {
    return 0.5f * x * (1.0f + erff(x * 0.70710678118654752f));
}

// ---------------------------------------------------------------------------
// Kernel 1: build the two scalar-bias tables
// ---------------------------------------------------------------------------
__global__ void build_tables_kernel(
    const float* __restrict__ muD, const float* __restrict__ sgD, const float* __restrict__ bD,
    const float* __restrict__ muE, const float* __restrict__ sgE, const float* __restrict__ bE,
    const float* __restrict__ W1,  const float* __restrict__ b1,
    const float* __restrict__ W2,  const float* __restrict__ b2,
    int KG)
{
    int t     = blockIdx.x * blockDim.x + threadIdx.x;
    int which = blockIdx.y;
    if (t >= NTAB) return;

    const float* mu = which ? muE : muD;
    const float* sg = which ? sgE : sgD;
    const float* bb = which ? bE  : bD;

    const float step = (TAB_HI - TAB_LO) / (float)NTAB;

    float f[2];
    #pragma unroll
    for (int p = 0; p < 2; ++p) {
        float x = TAB_LO + (float)(t + p) * step;
        float psi[16];
        for (int k = 0; k < KG; ++k) {
            float s  = sg[k];
            float z  = (x + bb[k] - mu[k]) / s;
            float in = 0.3989422804014327f / s;
            psi[k]   = expf(-0.5f * z * z) * in;
        }
        float hv[16];
        for (int l = 0; l < KG; ++l) {
            float acc = b1[l];
            for (int k = 0; k < KG; ++k) acc += psi[k] * W1[l * KG + k];
            hv[l] = gelu_exact(acc);
        }
        float o = b2[0];
        for (int l = 0; l < KG; ++l) o += hv[l] * W2[l];
        f[p] = o;
    }
    g_tab[which][t] = make_float2(f[0], f[1] - f[0]);
}

// ---------------------------------------------------------------------------
// helpers
// ---------------------------------------------------------------------------
__device__ __forceinline__ uint32_t f2tf(float x) {
    uint32_t u;
    asm("cvt.rna.tf32.f32 %0, %1;" : "=r"(u) : "f"(x));
    return u;
}

__device__ __forceinline__ void mma_tf32(
    float& c0, float& c1, float& c2, float& c3,
    uint32_t a0, uint32_t a1, uint32_t a2, uint32_t a3,
    uint32_t b0, uint32_t b1)
{
    asm volatile(
        "mma.sync.aligned.m16n8k8.row.col.f32.tf32.tf32.f32 "
        "{%0,%1,%2,%3}, {%4,%5,%6,%7}, {%8,%9}, {%0,%1,%2,%3};"
        : "+f"(c0), "+f"(c1), "+f"(c2), "+f"(c3)
        : "r"(a0), "r"(a1), "r"(a2), "r"(a3), "r"(b0), "r"(b1));
}

__device__ __forceinline__ void cp_async16(uint32_t dst, const void* src) {
    asm volatile("cp.async.cg.shared.global [%0], [%1], 16;"
                 :: "r"(dst), "l"(src));
}
__device__ __forceinline__ void cp_commit() {
    asm volatile("cp.async.commit_group;");
}
template <int N>
__device__ __forceinline__ void cp_wait() {
    asm volatile("cp.async.wait_group %0;" :: "n"(N));
}

__device__ __forceinline__ float lut(const float2* __restrict__ t, float x, float inv_step) {
    float tt = (x - TAB_LO) * inv_step;
    int ix = (int)tt;
    ix = min(max(ix, 0), NTAB - 1);
    float fr = tt - (float)ix;
    float2 e = t[ix];
    return fmaf(fr, e.y, e.x);
}

// ---------------------------------------------------------------------------
// Kernel 2: fused flash attention, tf32 MMA, cp.async pipeline, 512 threads.
// 16 warps = 4 m-stripes (16 rows) x 4 key-quarters (16 keys).
// ---------------------------------------------------------------------------
__global__ void __launch_bounds__(NTHREADS, 1)
attn_kernel(const float* __restrict__ Q, const float* __restrict__ K,
            const float* __restrict__ V,
            const float* __restrict__ dist, const float* __restrict__ ener,
            const int*   __restrict__ mask,
            float* __restrict__ out)
{
    extern __shared__ float sm[];
    float*  Kb0  = sm;                        // [2] x 64 x KSTR (raw f32)
    float*  Kb1  = Kb0 + 64 * KSTR;
    float*  Vb0  = Kb1 + 64 * KSTR;           // [2] x 64 x VSTR (raw f32)
    float*  Vb1  = Vb0 + 64 * VSTR;
    float*  Mred = Vb1 + 64 * VSTR;           // [4][64]
    float*  Lred = Mred + 256;                // [4][64]
    float2* tD   = (float2*)(Lred + 256);     // NTAB
    float2* tE   = tD + NTAB;                 // NTAB

    const int tid  = threadIdx.x;
    const int w    = tid >> 5;
    const int lane = tid & 31;
    const int g    = lane >> 2;
    const int qd   = lane & 3;
    const int mw   = w >> 2;          // m-stripe 0..3
    const int qt   = w & 3;           // key-quarter 0..3
    const int r_lo = mw * 16 + g;
    const int r_hi = r_lo + 8;
    const int nbase = qt * 16;
    const int h    = blockIdx.y;
    const int q0   = blockIdx.x * BM;

    // copy geometry: 512 threads, 2 float4 rows each (rows cr, cr+32)
    const int cr  = tid >> 4;          // 0..31
    const int cc4 = (tid & 15) << 2;

    const float* Kg0 = K + (size_t)h * S_LEN * DH;
    const float* Vg0 = V + (size_t)h * S_LEN * DH;

    const uint32_t kb0s = (uint32_t)__cvta_generic_to_shared(Kb0);
    const uint32_t kb1s = (uint32_t)__cvta_generic_to_shared(Kb1);
    const uint32_t vb0s = (uint32_t)__cvta_generic_to_shared(Vb0);
    const uint32_t vb1s = (uint32_t)__cvta_generic_to_shared(Vb1);
    const uint32_t koff = (uint32_t)((cr * KSTR + cc4) * 4);
    const uint32_t voff = (uint32_t)((cr * VSTR + cc4) * 4);

    // ---- stage tables ----
    for (int i = tid; i < NTAB; i += NTHREADS) {
        tD[i] = g_tab[0][i];
        tE[i] = g_tab[1][i];
    }

    // ---- prologue: K/V tile 0 ----
    {
        cp_async16(kb0s + koff,                    Kg0 + cr * DH + cc4);
        cp_async16(kb0s + koff + 32 * KSTR * 4,    Kg0 + (cr + 32) * DH + cc4);
        cp_async16(vb0s + voff,                    Vg0 + cr * DH + cc4);
        cp_async16(vb0s + voff + 32 * VSTR * 4,    Vg0 + (cr + 32) * DH + cc4);
        cp_commit();
    }

    // ---- Q fragments -> registers ----
    const float SCALE = 0.08838834764831845f;   // 1/sqrt(2*D)
    const float* Qg = Q + ((size_t)h * S_LEN + q0) * DH;
    uint32_t qf[8][4];
    #pragma unroll
    for (int kf = 0; kf < 8; ++kf) {
        int k0 = kf * 8;
        qf[kf][0] = f2tf(Qg[r_lo * DH + k0 + qd]     * SCALE);
        qf[kf][1] = f2tf(Qg[r_hi * DH + k0 + qd]     * SCALE);
        qf[kf][2] = f2tf(Qg[r_lo * DH + k0 + qd + 4] * SCALE);
        qf[kf][3] = f2tf(Qg[r_hi * DH + k0 + qd + 4] * SCALE);
    }

    float o[8][4];
    #pragma unroll
    for (int j = 0; j < 8; ++j)
        #pragma unroll
        for (int c = 0; c < 4; ++c) o[j][c] = 0.f;

    float m_lo = -1e30f, m_hi = -1e30f, l_lo = 0.f, l_hi = 0.f;
    const float inv_step = (float)NTAB / (TAB_HI - TAB_LO);

    for (int jt = 0; jt < S_LEN / BN; ++jt) {
        const int buf = jt & 1;
        const float* Ksb = buf ? Kb1 : Kb0;
        const float* Vsb = buf ? Vb1 : Vb0;

        // ---- issue next tile's K/V copy ----
        if (jt + 1 < S_LEN / BN) {
            const float* Kg = Kg0 + (size_t)(jt + 1) * BN * DH;
            const float* Vg = Vg0 + (size_t)(jt + 1) * BN * DH;
            uint32_t kd = (buf ? kb0s : kb1s) + koff;
            uint32_t vd = (buf ? vb0s : vb1s) + voff;
            cp_async16(kd,                 Kg + cr * DH + cc4);
            cp_async16(kd + 32 * KSTR * 4, Kg + (cr + 32) * DH + cc4);
            cp_async16(vd,                 Vg + cr * DH + cc4);
            cp_async16(vd + 32 * VSTR * 4, Vg + (cr + 32) * DH + cc4);
            cp_commit();
        }

        // ---- bias-stream loads for THIS tile (in flight during QK mma) ----
        size_t base_lo = ((size_t)h * S_LEN + q0 + r_lo) * S_LEN
                         + (size_t)(jt * BN + nbase + 2 * qd);
        size_t base_hi = base_lo + (size_t)8 * S_LEN;

        float2 dlo[2], dhi[2], elo[2], ehi[2];
        int2   mlo[2], mhi[2];
        #pragma unroll
        for (int j = 0; j < 2; ++j) {
            dlo[j] = *(const float2*)(dist + base_lo + j * 8);
            dhi[j] = *(const float2*)(dist + base_hi + j * 8);
            elo[j] = *(const float2*)(ener + base_lo + j * 8);
            ehi[j] = *(const float2*)(ener + base_hi + j * 8);
            mlo[j] = *(const int2*)(mask + base_lo + j * 8);
            mhi[j] = *(const int2*)(mask + base_hi + j * 8);
        }

        if (jt + 1 < S_LEN / BN) cp_wait<1>(); else cp_wait<0>();
        __syncthreads();

        // ---- S = Q K^T : warp computes m16 x n16 (2 n8-subtiles) ----
        float s[2][4];
        #pragma unroll
        for (int j = 0; j < 2; ++j)
            #pragma unroll
            for (int c = 0; c < 4; ++c) s[j][c] = 0.f;

        #pragma unroll
        for (int kf = 0; kf < 8; ++kf) {
            #pragma unroll
            for (int j = 0; j < 2; ++j) {
                int key = nbase + j * 8 + g;
                uint32_t b0 = f2tf(Ksb[key * KSTR + kf * 8 + qd]);
                uint32_t b1 = f2tf(Ksb[key * KSTR + kf * 8 + qd + 4]);
                mma_tf32(s[j][0], s[j][1], s[j][2], s[j][3],
                         qf[kf][0], qf[kf][1], qf[kf][2], qf[kf][3], b0, b1);
            }
        }

        // ---- apply biases + mask ----
        #pragma unroll
        for (int j = 0; j < 2; ++j) {
            float v00 = s[j][0] + lut(tD, dlo[j].x, inv_step) + lut(tE, elo[j].x, inv_step);
            float v01 = s[j][1] + lut(tD, dlo[j].y, inv_step) + lut(tE, elo[j].y, inv_step);
            float v10 = s[j][2] + lut(tD, dhi[j].x, inv_step) + lut(tE, ehi[j].x, inv_step);
            float v11 = s[j][3] + lut(tD, dhi[j].y, inv_step) + lut(tE, ehi[j].y, inv_step);
            s[j][0] = (mlo[j].x == 0) ? -1e9f : v00;
            s[j][1] = (mlo[j].y == 0) ? -1e9f : v01;
            s[j][2] = (mhi[j].x == 0) ? -1e9f : v10;
            s[j][3] = (mhi[j].y == 0) ? -1e9f : v11;
        }

        // ---- online softmax (across 4 quarters via smem) ----
        float pl = fmaxf(fmaxf(s[0][0], s[0][1]), fmaxf(s[1][0], s[1][1]));
        float ph = fmaxf(fmaxf(s[0][2], s[0][3]), fmaxf(s[1][2], s[1][3]));
        pl = fmaxf(pl, __shfl_xor_sync(0xffffffffu, pl, 1));
        pl = fmaxf(pl, __shfl_xor_sync(0xffffffffu, pl, 2));
        ph = fmaxf(ph, __shfl_xor_sync(0xffffffffu, ph, 1));
        ph = fmaxf(ph, __shfl_xor_sync(0xffffffffu, ph, 2));
        if (qd == 0) {
            Mred[qt * 64 + r_lo] = pl;
            Mred[qt * 64 + r_hi] = ph;
        }
        __syncthreads();
        float nm_lo = fmaxf(fmaxf(Mred[r_lo], Mred[64 + r_lo]),
                            fmaxf(Mred[128 + r_lo], Mred[192 + r_lo]));
        float nm_hi = fmaxf(fmaxf(Mred[r_hi], Mred[64 + r_hi]),
                            fmaxf(Mred[128 + r_hi], Mred[192 + r_hi]));
        nm_lo = fmaxf(m_lo, nm_lo);
        nm_hi = fmaxf(m_hi, nm_hi);
        float c_lo = __expf(m_lo - nm_lo);
        float c_hi = __expf(m_hi - nm_hi);
        m_lo = nm_lo; m_hi = nm_hi;

        float sl = 0.f, sh = 0.f;
        #pragma unroll
        for (int j = 0; j < 2; ++j) {
            s[j][0] = __expf(s[j][0] - nm_lo); sl += s[j][0];
            s[j][1] = __expf(s[j][1] - nm_lo); sl += s[j][1];
            s[j][2] = __expf(s[j][2] - nm_hi); sh += s[j][2];
            s[j][3] = __expf(s[j][3] - nm_hi); sh += s[j][3];
        }
        sl += __shfl_xor_sync(0xffffffffu, sl, 1);
        sl += __shfl_xor_sync(0xffffffffu, sl, 2);
        sh += __shfl_xor_sync(0xffffffffu, sh, 1);
        sh += __shfl_xor_sync(0xffffffffu, sh, 2);
        l_lo = l_lo * c_lo + sl;
        l_hi = l_hi * c_hi + sh;

        #pragma unroll
        for (int j = 0; j < 8; ++j) {
            o[j][0] *= c_lo; o[j][1] *= c_lo;
            o[j][2] *= c_hi; o[j][3] *= c_hi;
        }

        // ---- O += P V over this quarter's 16 keys (2 k8 fragments) ----
        const int l0 = g * 4 + (qd >> 1);
        const int l1 = l0 + 2;
        const bool odd = (qd & 1);
        #pragma unroll
        for (int kf = 0; kf < 2; ++kf) {
            float v0 = __shfl_sync(0xffffffffu, s[kf][0], l0);
            float v1 = __shfl_sync(0xffffffffu, s[kf][1], l0);
            float v2 = __shfl_sync(0xffffffffu, s[kf][2], l0);
            float v3 = __shfl_sync(0xffffffffu, s[kf][3], l0);
            float w0 = __shfl_sync(0xffffffffu, s[kf][0], l1);
            float w1 = __shfl_sync(0xffffffffu, s[kf][1], l1);
            float w2 = __shfl_sync(0xffffffffu, s[kf][2], l1);
            float w3 = __shfl_sync(0xffffffffu, s[kf][3], l1);
            uint32_t a0 = f2tf(odd ? v1 : v0);
            uint32_t a1 = f2tf(odd ? v3 : v2);
            uint32_t a2 = f2tf(odd ? w1 : w0);
            uint32_t a3 = f2tf(odd ? w3 : w2);
            int vr = nbase + kf * 8 + qd;
            #pragma unroll
            for (int j = 0; j < 8; ++j) {
                uint32_t b0 = f2tf(Vsb[vr * VSTR + j * 8 + g]);
                uint32_t b1 = f2tf(Vsb[(vr + 4) * VSTR + j * 8 + g]);
                mma_tf32(o[j][0], o[j][1], o[j][2], o[j][3], a0, a1, a2, a3, b0, b1);
            }
        }
        __syncthreads();   // buffer reads done before refill
    }

    // ---- epilogue: combine 4 quarters, normalize, store ----
    if (qd == 0) {
        Lred[qt * 64 + r_lo] = l_lo;
        Lred[qt * 64 + r_hi] = l_hi;
    }
    // quarters 1..3 dump partial O into dead K/V buffers
    float* pbuf = (qt == 1) ? Kb0 : (qt == 2) ? Kb1 : Vb0;
    if (qt != 0) {
        #pragma unroll
        for (int j = 0; j < 8; ++j) {
            *(float2*)&pbuf[r_lo * KSTR + j * 8 + 2 * qd] = make_float2(o[j][0], o[j][1]);
            *(float2*)&pbuf[r_hi * KSTR + j * 8 + 2 * qd] = make_float2(o[j][2], o[j][3]);
        }
    }
    __syncthreads();
    if (qt == 0) {
        float il_lo = 1.0f / (Lred[r_lo] + Lred[64 + r_lo] + Lred[128 + r_lo] + Lred[192 + r_lo]);
        float il_hi = 1.0f / (Lred[r_hi] + Lred[64 + r_hi] + Lred[128 + r_hi] + Lred[192 + r_hi]);
        float* og = out + ((size_t)h * S_LEN + q0) * DH;
        #pragma unroll
        for (int j = 0; j < 8; ++j) {
            int cidx = j * 8 + 2 * qd;
            float2 a0 = *(float2*)&Kb0[r_lo * KSTR + cidx];
            float2 b0 = *(float2*)&Kb1[r_lo * KSTR + cidx];
            float2 c0 = *(float2*)&Vb0[r_lo * KSTR + cidx];
            float2 a1 = *(float2*)&Kb0[r_hi * KSTR + cidx];
            float2 b1 = *(float2*)&Kb1[r_hi * KSTR + cidx];
            float2 c1 = *(float2*)&Vb0[r_hi * KSTR + cidx];
            float2 r0 = make_float2((o[j][0] + a0.x + b0.x + c0.x) * il_lo,
                                    (o[j][1] + a0.y + b0.y + c0.y) * il_lo);
            float2 r1 = make_float2((o[j][2] + a1.x + b1.x + c1.x) * il_hi,
                                    (o[j][3] + a1.y + b1.y + c1.y) * il_hi);
            *(float2*)(og + r_lo * DH + cidx) = r0;
            *(float2*)(og + r_hi * DH + cidx) = r1;
        }
    }
}

// ---------------------------------------------------------------------------
// Launch
// ---------------------------------------------------------------------------
extern "C" void kernel_launch(void* const* d_in, const int* in_sizes, int n_in,
                              void* d_out, int out_size)
{
    const float* Q    = (const float*)d_in[0];
    const float* K    = (const float*)d_in[1];
    const float* V    = (const float*)d_in[2];
    const float* dist = (const float*)d_in[3];
    const float* ener = (const float*)d_in[4];
    const int*   mask = (const int*)  d_in[5];
    const float* muD  = (const float*)d_in[6];
    const float* sgD  = (const float*)d_in[7];
    const float* bD   = (const float*)d_in[8];
    const float* muE  = (const float*)d_in[9];
    const float* sgE  = (const float*)d_in[10];
    const float* bE   = (const float*)d_in[11];
    const float* W1   = (const float*)d_in[12];
    const float* b1   = (const float*)d_in[13];
    const float* W2   = (const float*)d_in[14];
    const float* b2   = (const float*)d_in[15];
    float* out = (float*)d_out;

    int KG = in_sizes[6];
    if (KG > 16) KG = 16;

    build_tables_kernel<<<dim3(NTAB / 256, 2), 256>>>(
        muD, sgD, bD, muE, sgE, bE, W1, b1, W2, b2, KG);

    const int SMEM_BYTES = (2 * 64 * KSTR + 2 * 64 * VSTR + 512) * (int)sizeof(float)
                         + 2 * NTAB * (int)sizeof(float2);
    cudaFuncSetAttribute(attn_kernel,
                         cudaFuncAttributeMaxDynamicSharedMemorySize, SMEM_BYTES);

    attn_kernel<<<dim3(S_LEN / BM, HEADS), NTHREADS, SMEM_BYTES>>>(
        Q, K, V, dist, ener, mask, out);
}

// round 8
// speedup vs baseline: 1.5351x; 1.0234x over previous
#include <cuda_runtime.h>
#include <math.h>
#include <stdint.h>

// Problem shapes (fixed)
#define S_LEN 1024
#define HEADS 8
#define DH    64
#define BM    64
#define BN    64
#define KSTR  68
#define VSTR  72
#define NTHREADS 512

// Bias lookup tables
#define NTAB   2048
#define TAB_LO (-0.5f)
#define TAB_HI (10.5f)

__device__ float2 g_tab[2][NTAB];

__device__ __forceinline__ float gelu_exact(float x) {
    return 0.5f * x * (1.0f + erff(x * 0.70710678118654752f));
}

// ---------------------------------------------------------------------------
// Kernel 1: build the two scalar-bias tables
// ---------------------------------------------------------------------------
__global__ void build_tables_kernel(
    const float* __restrict__ muD, const float* __restrict__ sgD, const float* __restrict__ bD,
    const float* __restrict__ muE, const float* __restrict__ sgE, const float* __restrict__ bE,
    const float* __restrict__ W1,  const float* __restrict__ b1,
    const float* __restrict__ W2,  const float* __restrict__ b2,
    int KG)
{
    int t     = blockIdx.x * blockDim.x + threadIdx.x;
    int which = blockIdx.y;
    if (t >= NTAB) return;

    const float* mu = which ? muE : muD;
    const float* sg = which ? sgE : sgD;
    const float* bb = which ? bE  : bD;

    const float step = (TAB_HI - TAB_LO) / (float)NTAB;

    float f[2];
    #pragma unroll
    for (int p = 0; p < 2; ++p) {
        float x = TAB_LO + (float)(t + p) * step;
        float psi[16];
        for (int k = 0; k < KG; ++k) {
            float s  = sg[k];
            float z  = (x + bb[k] - mu[k]) / s;
            float in = 0.3989422804014327f / s;
            psi[k]   = expf(-0.5f * z * z) * in;
        }
        float hv[16];
        for (int l = 0; l < KG; ++l) {
            float acc = b1[l];
            for (int k = 0; k < KG; ++k) acc += psi[k] * W1[l * KG + k];
            hv[l] = gelu_exact(acc);
        }
        float o = b2[0];
        for (int l = 0; l < KG; ++l) o += hv[l] * W2[l];
        f[p] = o;
    }
    g_tab[which][t] = make_float2(f[0], f[1] - f[0]);
}

// ---------------------------------------------------------------------------
// helpers
// ---------------------------------------------------------------------------
__device__ __forceinline__ uint32_t f2tf(float x) {
    uint32_t u;
    asm("cvt.rna.tf32.f32 %0, %1;" : "=r"(u) : "f"(x));
    return u;
}

__device__ __forceinline__ void mma_tf32(
    float& c0, float& c1, float& c2, float& c3,
    uint32_t a0, uint32_t a1, uint32_t a2, uint32_t a3,
    uint32_t b0, uint32_t b1)
{
    asm volatile(
        "mma.sync.aligned.m16n8k8.row.col.f32.tf32.tf32.f32 "
        "{%0,%1,%2,%3}, {%4,%5,%6,%7}, {%8,%9}, {%0,%1,%2,%3};"
        : "+f"(c0), "+f"(c1), "+f"(c2), "+f"(c3)
        : "r"(a0), "r"(a1), "r"(a2), "r"(a3), "r"(b0), "r"(b1));
}

__device__ __forceinline__ void cp_async16(uint32_t dst, const void* src) {
    asm volatile("cp.async.cg.shared.global [%0], [%1], 16;"
                 :: "r"(dst), "l"(src));
}
__device__ __forceinline__ void cp_commit() {
    asm volatile("cp.async.commit_group;");
}
template <int N>
__device__ __forceinline__ void cp_wait() {
    asm volatile("cp.async.wait_group %0;" :: "n"(N));
}

__device__ __forceinline__ float lut(const float2* __restrict__ t, float x, float inv_step) {
    float tt = (x - TAB_LO) * inv_step;
    int ix = (int)tt;
    ix = min(max(ix, 0), NTAB - 1);
    float fr = tt - (float)ix;
    float2 e = t[ix];
    return fmaf(fr, e.y, e.x);
}

// ---------------------------------------------------------------------------
// Kernel 2: fused flash attention, tf32 MMA, cp.async pipeline, 512 threads.
// 16 warps = 4 m-stripes x 4 key-quarters; each quarter keeps an INDEPENDENT
// online softmax (local m/l/o), merged once in the epilogue. One barrier/iter.
// ---------------------------------------------------------------------------
__global__ void __launch_bounds__(NTHREADS, 1)
attn_kernel(const float* __restrict__ Q, const float* __restrict__ K,
            const float* __restrict__ V,
            const float* __restrict__ dist, const float* __restrict__ ener,
            const int*   __restrict__ mask,
            float* __restrict__ out)
{
    extern __shared__ float sm[];
    float*  Kb0  = sm;                        // [2] x 64 x KSTR (raw f32)
    float*  Kb1  = Kb0 + 64 * KSTR;
    float*  Vb0  = Kb1 + 64 * KSTR;           // [2] x 64 x VSTR (raw f32)
    float*  Vb1  = Vb0 + 64 * VSTR;
    float*  Mred = Vb1 + 64 * VSTR;           // [4][64] (epilogue only)
    float*  Lred = Mred + 256;                // [4][64] (epilogue only)
    float2* tD   = (float2*)(Lred + 256);     // NTAB
    float2* tE   = tD + NTAB;                 // NTAB

    const int tid  = threadIdx.x;
    const int w    = tid >> 5;
    const int lane = tid & 31;
    const int g    = lane >> 2;
    const int qd   = lane & 3;
    const int mw   = w >> 2;          // m-stripe 0..3
    const int qt   = w & 3;           // key-quarter 0..3
    const int r_lo = mw * 16 + g;
    const int r_hi = r_lo + 8;
    const int nbase = qt * 16;
    const int h    = blockIdx.y;
    const int q0   = blockIdx.x * BM;

    // copy geometry: 512 threads, 2 float4 rows each (rows cr, cr+32)
    const int cr  = tid >> 4;          // 0..31
    const int cc4 = (tid & 15) << 2;

    const float* Kg0 = K + (size_t)h * S_LEN * DH;
    const float* Vg0 = V + (size_t)h * S_LEN * DH;

    const uint32_t kb0s = (uint32_t)__cvta_generic_to_shared(Kb0);
    const uint32_t kb1s = (uint32_t)__cvta_generic_to_shared(Kb1);
    const uint32_t vb0s = (uint32_t)__cvta_generic_to_shared(Vb0);
    const uint32_t vb1s = (uint32_t)__cvta_generic_to_shared(Vb1);
    const uint32_t koff = (uint32_t)((cr * KSTR + cc4) * 4);
    const uint32_t voff = (uint32_t)((cr * VSTR + cc4) * 4);

    // ---- stage tables ----
    for (int i = tid; i < NTAB; i += NTHREADS) {
        tD[i] = g_tab[0][i];
        tE[i] = g_tab[1][i];
    }

    // ---- prologue: K/V tile 0 ----
    {
        cp_async16(kb0s + koff,                    Kg0 + cr * DH + cc4);
        cp_async16(kb0s + koff + 32 * KSTR * 4,    Kg0 + (cr + 32) * DH + cc4);
        cp_async16(vb0s + voff,                    Vg0 + cr * DH + cc4);
        cp_async16(vb0s + voff + 32 * VSTR * 4,    Vg0 + (cr + 32) * DH + cc4);
        cp_commit();
    }

    // ---- Q fragments -> registers ----
    const float SCALE = 0.08838834764831845f;   // 1/sqrt(2*D)
    const float* Qg = Q + ((size_t)h * S_LEN + q0) * DH;
    uint32_t qf[8][4];
    #pragma unroll
    for (int kf = 0; kf < 8; ++kf) {
        int k0 = kf * 8;
        qf[kf][0] = f2tf(Qg[r_lo * DH + k0 + qd]     * SCALE);
        qf[kf][1] = f2tf(Qg[r_hi * DH + k0 + qd]     * SCALE);
        qf[kf][2] = f2tf(Qg[r_lo * DH + k0 + qd + 4] * SCALE);
        qf[kf][3] = f2tf(Qg[r_hi * DH + k0 + qd + 4] * SCALE);
    }

    float o[8][4];
    #pragma unroll
    for (int j = 0; j < 8; ++j)
        #pragma unroll
        for (int c = 0; c < 4; ++c) o[j][c] = 0.f;

    float m_lo = -1e30f, m_hi = -1e30f, l_lo = 0.f, l_hi = 0.f;
    const float inv_step = (float)NTAB / (TAB_HI - TAB_LO);

    for (int jt = 0; jt < S_LEN / BN; ++jt) {
        const int buf = jt & 1;
        const float* Ksb = buf ? Kb1 : Kb0;
        const float* Vsb = buf ? Vb1 : Vb0;

        // ---- wait for this tile's K/V; single barrier also retires all
        //      reads of the other buffer from the previous iteration ----
        cp_wait<0>();
        __syncthreads();

        // ---- issue next tile's K/V copy (consumed only after next barrier) ----
        if (jt + 1 < S_LEN / BN) {
            const float* Kg = Kg0 + (size_t)(jt + 1) * BN * DH;
            const float* Vg = Vg0 + (size_t)(jt + 1) * BN * DH;
            uint32_t kd = (buf ? kb0s : kb1s) + koff;
            uint32_t vd = (buf ? vb0s : vb1s) + voff;
            cp_async16(kd,                 Kg + cr * DH + cc4);
            cp_async16(kd + 32 * KSTR * 4, Kg + (cr + 32) * DH + cc4);
            cp_async16(vd,                 Vg + cr * DH + cc4);
            cp_async16(vd + 32 * VSTR * 4, Vg + (cr + 32) * DH + cc4);
            cp_commit();
        }

        // ---- bias-stream loads for THIS tile (land during QK mma) ----
        size_t base_lo = ((size_t)h * S_LEN + q0 + r_lo) * S_LEN
                         + (size_t)(jt * BN + nbase + 2 * qd);
        size_t base_hi = base_lo + (size_t)8 * S_LEN;

        float2 dlo[2], dhi[2], elo[2], ehi[2];
        int2   mlo[2], mhi[2];
        #pragma unroll
        for (int j = 0; j < 2; ++j) {
            dlo[j] = *(const float2*)(dist + base_lo + j * 8);
            dhi[j] = *(const float2*)(dist + base_hi + j * 8);
            elo[j] = *(const float2*)(ener + base_lo + j * 8);
            ehi[j] = *(const float2*)(ener + base_hi + j * 8);
            mlo[j] = *(const int2*)(mask + base_lo + j * 8);
            mhi[j] = *(const int2*)(mask + base_hi + j * 8);
        }

        // ---- S = Q K^T : warp computes m16 x n16 (2 n8-subtiles) ----
        float s[2][4];
        #pragma unroll
        for (int j = 0; j < 2; ++j)
            #pragma unroll
            for (int c = 0; c < 4; ++c) s[j][c] = 0.f;

        #pragma unroll
        for (int kf = 0; kf < 8; ++kf) {
            #pragma unroll
            for (int j = 0; j < 2; ++j) {
                int key = nbase + j * 8 + g;
                uint32_t b0 = f2tf(Ksb[key * KSTR + kf * 8 + qd]);
                uint32_t b1 = f2tf(Ksb[key * KSTR + kf * 8 + qd + 4]);
                mma_tf32(s[j][0], s[j][1], s[j][2], s[j][3],
                         qf[kf][0], qf[kf][1], qf[kf][2], qf[kf][3], b0, b1);
            }
        }

        // ---- apply biases + mask ----
        #pragma unroll
        for (int j = 0; j < 2; ++j) {
            float v00 = s[j][0] + lut(tD, dlo[j].x, inv_step) + lut(tE, elo[j].x, inv_step);
            float v01 = s[j][1] + lut(tD, dlo[j].y, inv_step) + lut(tE, elo[j].y, inv_step);
            float v10 = s[j][2] + lut(tD, dhi[j].x, inv_step) + lut(tE, ehi[j].x, inv_step);
            float v11 = s[j][3] + lut(tD, dhi[j].y, inv_step) + lut(tE, ehi[j].y, inv_step);
            s[j][0] = (mlo[j].x == 0) ? -1e9f : v00;
            s[j][1] = (mlo[j].y == 0) ? -1e9f : v01;
            s[j][2] = (mhi[j].x == 0) ? -1e9f : v10;
            s[j][3] = (mhi[j].y == 0) ? -1e9f : v11;
        }

        // ---- quarter-local online softmax (intra-warp only, no barrier) ----
        float pl = fmaxf(fmaxf(s[0][0], s[0][1]), fmaxf(s[1][0], s[1][1]));
        float ph = fmaxf(fmaxf(s[0][2], s[0][3]), fmaxf(s[1][2], s[1][3]));
        pl = fmaxf(pl, __shfl_xor_sync(0xffffffffu, pl, 1));
        pl = fmaxf(pl, __shfl_xor_sync(0xffffffffu, pl, 2));
        ph = fmaxf(ph, __shfl_xor_sync(0xffffffffu, ph, 1));
        ph = fmaxf(ph, __shfl_xor_sync(0xffffffffu, ph, 2));

        float nm_lo = fmaxf(m_lo, pl);
        float nm_hi = fmaxf(m_hi, ph);
        float c_lo = __expf(m_lo - nm_lo);
        float c_hi = __expf(m_hi - nm_hi);
        m_lo = nm_lo; m_hi = nm_hi;

        float sl = 0.f, sh = 0.f;
        #pragma unroll
        for (int j = 0; j < 2; ++j) {
            s[j][0] = __expf(s[j][0] - nm_lo); sl += s[j][0];
            s[j][1] = __expf(s[j][1] - nm_lo); sl += s[j][1];
            s[j][2] = __expf(s[j][2] - nm_hi); sh += s[j][2];
            s[j][3] = __expf(s[j][3] - nm_hi); sh += s[j][3];
        }
        sl += __shfl_xor_sync(0xffffffffu, sl, 1);
        sl += __shfl_xor_sync(0xffffffffu, sl, 2);
        sh += __shfl_xor_sync(0xffffffffu, sh, 1);
        sh += __shfl_xor_sync(0xffffffffu, sh, 2);
        l_lo = l_lo * c_lo + sl;
        l_hi = l_hi * c_hi + sh;

        #pragma unroll
        for (int j = 0; j < 8; ++j) {
            o[j][0] *= c_lo; o[j][1] *= c_lo;
            o[j][2] *= c_hi; o[j][3] *= c_hi;
        }

        // ---- O += P V over this quarter's 16 keys (2 k8 fragments) ----
        const int l0 = g * 4 + (qd >> 1);
        const int l1 = l0 + 2;
        const bool odd = (qd & 1);
        #pragma unroll
        for (int kf = 0; kf < 2; ++kf) {
            float v0 = __shfl_sync(0xffffffffu, s[kf][0], l0);
            float v1 = __shfl_sync(0xffffffffu, s[kf][1], l0);
            float v2 = __shfl_sync(0xffffffffu, s[kf][2], l0);
            float v3 = __shfl_sync(0xffffffffu, s[kf][3], l0);
            float w0 = __shfl_sync(0xffffffffu, s[kf][0], l1);
            float w1 = __shfl_sync(0xffffffffu, s[kf][1], l1);
            float w2 = __shfl_sync(0xffffffffu, s[kf][2], l1);
            float w3 = __shfl_sync(0xffffffffu, s[kf][3], l1);
            uint32_t a0 = f2tf(odd ? v1 : v0);
            uint32_t a1 = f2tf(odd ? v3 : v2);
            uint32_t a2 = f2tf(odd ? w1 : w0);
            uint32_t a3 = f2tf(odd ? w3 : w2);
            int vr = nbase + kf * 8 + qd;
            #pragma unroll
            for (int j = 0; j < 8; ++j) {
                uint32_t b0 = f2tf(Vsb[vr * VSTR + j * 8 + g]);
                uint32_t b1 = f2tf(Vsb[(vr + 4) * VSTR + j * 8 + g]);
                mma_tf32(o[j][0], o[j][1], o[j][2], o[j][3], a0, a1, a2, a3, b0, b1);
            }
        }
    }

    // ---- epilogue: max-merge the 4 independent quarter softmaxes ----
    if (qd == 0) {
        Mred[qt * 64 + r_lo] = m_lo;
        Mred[qt * 64 + r_hi] = m_hi;
        Lred[qt * 64 + r_lo] = l_lo;
        Lred[qt * 64 + r_hi] = l_hi;
    }
    __syncthreads();
    float M_lo = fmaxf(fmaxf(Mred[r_lo], Mred[64 + r_lo]),
                       fmaxf(Mred[128 + r_lo], Mred[192 + r_lo]));
    float M_hi = fmaxf(fmaxf(Mred[r_hi], Mred[64 + r_hi]),
                       fmaxf(Mred[128 + r_hi], Mred[192 + r_hi]));
    float sc_lo = __expf(m_lo - M_lo);
    float sc_hi = __expf(m_hi - M_hi);

    // quarters 1..3 dump scaled partial O into dead K/V buffers
    float* pbuf = (qt == 1) ? Kb0 : (qt == 2) ? Kb1 : Vb0;
    if (qt != 0) {
        #pragma unroll
        for (int j = 0; j < 8; ++j) {
            *(float2*)&pbuf[r_lo * KSTR + j * 8 + 2 * qd] =
                make_float2(o[j][0] * sc_lo, o[j][1] * sc_lo);
            *(float2*)&pbuf[r_hi * KSTR + j * 8 + 2 * qd] =
                make_float2(o[j][2] * sc_hi, o[j][3] * sc_hi);
        }
    }
    __syncthreads();
    if (qt == 0) {
        float lt_lo = Lred[r_lo]       * __expf(Mred[r_lo]       - M_lo)
                    + Lred[64 + r_lo]  * __expf(Mred[64 + r_lo]  - M_lo)
                    + Lred[128 + r_lo] * __expf(Mred[128 + r_lo] - M_lo)
                    + Lred[192 + r_lo] * __expf(Mred[192 + r_lo] - M_lo);
        float lt_hi = Lred[r_hi]       * __expf(Mred[r_hi]       - M_hi)
                    + Lred[64 + r_hi]  * __expf(Mred[64 + r_hi]  - M_hi)
                    + Lred[128 + r_hi] * __expf(Mred[128 + r_hi] - M_hi)
                    + Lred[192 + r_hi] * __expf(Mred[192 + r_hi] - M_hi);
        float il_lo = 1.0f / lt_lo;
        float il_hi = 1.0f / lt_hi;
        float* og = out + ((size_t)h * S_LEN + q0) * DH;
        #pragma unroll
        for (int j = 0; j < 8; ++j) {
            int cidx = j * 8 + 2 * qd;
            float2 a0 = *(float2*)&Kb0[r_lo * KSTR + cidx];
            float2 b0 = *(float2*)&Kb1[r_lo * KSTR + cidx];
            float2 c0 = *(float2*)&Vb0[r_lo * KSTR + cidx];
            float2 a1 = *(float2*)&Kb0[r_hi * KSTR + cidx];
            float2 b1 = *(float2*)&Kb1[r_hi * KSTR + cidx];
            float2 c1 = *(float2*)&Vb0[r_hi * KSTR + cidx];
            float2 r0 = make_float2((o[j][0] * sc_lo + a0.x + b0.x + c0.x) * il_lo,
                                    (o[j][1] * sc_lo + a0.y + b0.y + c0.y) * il_lo);
            float2 r1 = make_float2((o[j][2] * sc_hi + a1.x + b1.x + c1.x) * il_hi,
                                    (o[j][3] * sc_hi + a1.y + b1.y + c1.y) * il_hi);
            *(float2*)(og + r_lo * DH + cidx) = r0;
            *(float2*)(og + r_hi * DH + cidx) = r1;
        }
    }
}

// ---------------------------------------------------------------------------
// Launch
// ---------------------------------------------------------------------------
extern "C" void kernel_launch(void* const* d_in, const int* in_sizes, int n_in,
                              void* d_out, int out_size)
{
    const float* Q    = (const float*)d_in[0];
    const float* K    = (const float*)d_in[1];
    const float* V    = (const float*)d_in[2];
    const float* dist = (const float*)d_in[3];
    const float* ener = (const float*)d_in[4];
    const int*   mask = (const int*)  d_in[5];
    const float* muD  = (const float*)d_in[6];
    const float* sgD  = (const float*)d_in[7];
    const float* bD   = (const float*)d_in[8];
    const float* muE  = (const float*)d_in[9];
    const float* sgE  = (const float*)d_in[10];
    const float* bE   = (const float*)d_in[11];
    const float* W1   = (const float*)d_in[12];
    const float* b1   = (const float*)d_in[13];
    const float* W2   = (const float*)d_in[14];
    const float* b2   = (const float*)d_in[15];
    float* out = (float*)d_out;

    int KG = in_sizes[6];
    if (KG > 16) KG = 16;

    build_tables_kernel<<<dim3(NTAB / 256, 2), 256>>>(
        muD, sgD, bD, muE, sgE, bE, W1, b1, W2, b2, KG);

    const int SMEM_BYTES = (2 * 64 * KSTR + 2 * 64 * VSTR + 512) * (int)sizeof(float)
                         + 2 * NTAB * (int)sizeof(float2);
    cudaFuncSetAttribute(attn_kernel,
                         cudaFuncAttributeMaxDynamicSharedMemorySize, SMEM_BYTES);

    attn_kernel<<<dim3(S_LEN / BM, HEADS), NTHREADS, SMEM_BYTES>>>(
        Q, K, V, dist, ener, mask, out);
}

// round 9
// speedup vs baseline: 1.5910x; 1.0364x over previous
#include <cuda_runtime.h>
#include <math.h>
#include <stdint.h>

// Problem shapes (fixed)
#define S_LEN 1024
#define HEADS 8
#define DH    64
#define BM    32
#define BN    64
#define KSTR  68
#define VSTR  72
#define NTHREADS 256

// Bias lookup tables
#define NTAB   1024
#define TAB_LO (-0.5f)
#define TAB_HI (10.5f)

__device__ float2 g_tab[2][NTAB];

__device__ __forceinline__ float gelu_exact(float x) {
    return 0.5f * x * (1.0f + erff(x * 0.70710678118654752f));
}

// ---------------------------------------------------------------------------
// Kernel 1: build the two scalar-bias tables
// ---------------------------------------------------------------------------
__global__ void build_tables_kernel(
    const float* __restrict__ muD, const float* __restrict__ sgD, const float* __restrict__ bD,
    const float* __restrict__ muE, const float* __restrict__ sgE, const float* __restrict__ bE,
    const float* __restrict__ W1,  const float* __restrict__ b1,
    const float* __restrict__ W2,  const float* __restrict__ b2,
    int KG)
{
    int t     = blockIdx.x * blockDim.x + threadIdx.x;
    int which = blockIdx.y;
    if (t >= NTAB) return;

    const float* mu = which ? muE : muD;
    const float* sg = which ? sgE : sgD;
    const float* bb = which ? bE  : bD;

    const float step = (TAB_HI - TAB_LO) / (float)NTAB;

    float f[2];
    #pragma unroll
    for (int p = 0; p < 2; ++p) {
        float x = TAB_LO + (float)(t + p) * step;
        float psi[16];
        for (int k = 0; k < KG; ++k) {
            float s  = sg[k];
            float z  = (x + bb[k] - mu[k]) / s;
            float in = 0.3989422804014327f / s;
            psi[k]   = expf(-0.5f * z * z) * in;
        }
        float hv[16];
        for (int l = 0; l < KG; ++l) {
            float acc = b1[l];
            for (int k = 0; k < KG; ++k) acc += psi[k] * W1[l * KG + k];
            hv[l] = gelu_exact(acc);
        }
        float o = b2[0];
        for (int l = 0; l < KG; ++l) o += hv[l] * W2[l];
        f[p] = o;
    }
    g_tab[which][t] = make_float2(f[0], f[1] - f[0]);
}

// ---------------------------------------------------------------------------
// helpers
// ---------------------------------------------------------------------------
__device__ __forceinline__ uint32_t f2tf(float x) {
    uint32_t u;
    asm("cvt.rna.tf32.f32 %0, %1;" : "=r"(u) : "f"(x));
    return u;
}

__device__ __forceinline__ void mma_tf32(
    float& c0, float& c1, float& c2, float& c3,
    uint32_t a0, uint32_t a1, uint32_t a2, uint32_t a3,
    uint32_t b0, uint32_t b1)
{
    asm volatile(
        "mma.sync.aligned.m16n8k8.row.col.f32.tf32.tf32.f32 "
        "{%0,%1,%2,%3}, {%4,%5,%6,%7}, {%8,%9}, {%0,%1,%2,%3};"
        : "+f"(c0), "+f"(c1), "+f"(c2), "+f"(c3)
        : "r"(a0), "r"(a1), "r"(a2), "r"(a3), "r"(b0), "r"(b1));
}

__device__ __forceinline__ void cp_async16(uint32_t dst, const void* src) {
    asm volatile("cp.async.cg.shared.global [%0], [%1], 16;"
                 :: "r"(dst), "l"(src));
}
__device__ __forceinline__ void cp_commit() {
    asm volatile("cp.async.commit_group;");
}
template <int N>
__device__ __forceinline__ void cp_wait() {
    asm volatile("cp.async.wait_group %0;" :: "n"(N));
}

__device__ __forceinline__ float lut(const float2* __restrict__ t, float x, float inv_step) {
    float tt = (x - TAB_LO) * inv_step;
    int ix = (int)tt;
    ix = min(max(ix, 0), NTAB - 1);
    float fr = tt - (float)ix;
    float2 e = t[ix];
    return fmaf(fr, e.y, e.x);
}

// ---------------------------------------------------------------------------
// Kernel 2: fused flash attention, tf32 MMA, cp.async pipeline.
// BM=32 tile, 256 threads = 8 warps = 2 m-stripes x 4 key-quarters.
// 2 CTAs co-resident per SM; quarter-local softmax merged in epilogue.
// ---------------------------------------------------------------------------
__global__ void __launch_bounds__(NTHREADS, 2)
attn_kernel(const float* __restrict__ Q, const float* __restrict__ K,
            const float* __restrict__ V,
            const float* __restrict__ dist, const float* __restrict__ ener,
            const int*   __restrict__ mask,
            float* __restrict__ out)
{
    extern __shared__ float sm[];
    float*  Kb0  = sm;                        // [2] x 64 x KSTR (raw f32)
    float*  Kb1  = Kb0 + 64 * KSTR;
    float*  Vb0  = Kb1 + 64 * KSTR;           // [2] x 64 x VSTR (raw f32)
    float*  Vb1  = Vb0 + 64 * VSTR;
    float*  Mred = Vb1 + 64 * VSTR;           // [4][32] (epilogue only)
    float*  Lred = Mred + 128;                // [4][32] (epilogue only)
    float2* tD   = (float2*)(Lred + 128);     // NTAB
    float2* tE   = tD + NTAB;                 // NTAB

    const int tid  = threadIdx.x;
    const int w    = tid >> 5;
    const int lane = tid & 31;
    const int g    = lane >> 2;
    const int qd   = lane & 3;
    const int mw   = w >> 2;          // m-stripe 0..1
    const int qt   = w & 3;           // key-quarter 0..3
    const int r_lo = mw * 16 + g;
    const int r_hi = r_lo + 8;
    const int nbase = qt * 16;
    const int h    = blockIdx.y;
    const int q0   = blockIdx.x * BM;

    // copy geometry: 256 threads, 4 float4 rows each (rows cr + p*16)
    const int cr  = tid >> 4;          // 0..15
    const int cc4 = (tid & 15) << 2;

    const float* Kg0 = K + (size_t)h * S_LEN * DH;
    const float* Vg0 = V + (size_t)h * S_LEN * DH;

    const uint32_t kb0s = (uint32_t)__cvta_generic_to_shared(Kb0);
    const uint32_t kb1s = (uint32_t)__cvta_generic_to_shared(Kb1);
    const uint32_t vb0s = (uint32_t)__cvta_generic_to_shared(Vb0);
    const uint32_t vb1s = (uint32_t)__cvta_generic_to_shared(Vb1);
    const uint32_t koff = (uint32_t)((cr * KSTR + cc4) * 4);
    const uint32_t voff = (uint32_t)((cr * VSTR + cc4) * 4);

    // ---- stage tables ----
    for (int i = tid; i < NTAB; i += NTHREADS) {
        tD[i] = g_tab[0][i];
        tE[i] = g_tab[1][i];
    }

    // ---- prologue: K/V tile 0 ----
    {
        #pragma unroll
        for (int p = 0; p < 4; ++p) {
            int r = cr + p * 16;
            cp_async16(kb0s + koff + p * 16 * KSTR * 4, Kg0 + r * DH + cc4);
            cp_async16(vb0s + voff + p * 16 * VSTR * 4, Vg0 + r * DH + cc4);
        }
        cp_commit();
    }

    // ---- Q fragments -> registers ----
    const float SCALE = 0.08838834764831845f;   // 1/sqrt(2*D)
    const float* Qg = Q + ((size_t)h * S_LEN + q0) * DH;
    uint32_t qf[8][4];
    #pragma unroll
    for (int kf = 0; kf < 8; ++kf) {
        int k0 = kf * 8;
        qf[kf][0] = f2tf(Qg[r_lo * DH + k0 + qd]     * SCALE);
        qf[kf][1] = f2tf(Qg[r_hi * DH + k0 + qd]     * SCALE);
        qf[kf][2] = f2tf(Qg[r_lo * DH + k0 + qd + 4] * SCALE);
        qf[kf][3] = f2tf(Qg[r_hi * DH + k0 + qd + 4] * SCALE);
    }

    float o[8][4];
    #pragma unroll
    for (int j = 0; j < 8; ++j)
        #pragma unroll
        for (int c = 0; c < 4; ++c) o[j][c] = 0.f;

    float m_lo = -1e30f, m_hi = -1e30f, l_lo = 0.f, l_hi = 0.f;
    const float inv_step = (float)NTAB / (TAB_HI - TAB_LO);

    for (int jt = 0; jt < S_LEN / BN; ++jt) {
        const int buf = jt & 1;
        const float* Ksb = buf ? Kb1 : Kb0;
        const float* Vsb = buf ? Vb1 : Vb0;

        // ---- wait for this tile's K/V; barrier also retires prior reads ----
        cp_wait<0>();
        __syncthreads();

        // ---- issue next tile's K/V copy ----
        if (jt + 1 < S_LEN / BN) {
            const float* Kg = Kg0 + (size_t)(jt + 1) * BN * DH;
            const float* Vg = Vg0 + (size_t)(jt + 1) * BN * DH;
            uint32_t kd = (buf ? kb0s : kb1s) + koff;
            uint32_t vd = (buf ? vb0s : vb1s) + voff;
            #pragma unroll
            for (int p = 0; p < 4; ++p) {
                int r = cr + p * 16;
                cp_async16(kd + p * 16 * KSTR * 4, Kg + r * DH + cc4);
                cp_async16(vd + p * 16 * VSTR * 4, Vg + r * DH + cc4);
            }
            cp_commit();
        }

        // ---- bias-stream loads for THIS tile (land during QK mma) ----
        size_t base_lo = ((size_t)h * S_LEN + q0 + r_lo) * S_LEN
                         + (size_t)(jt * BN + nbase + 2 * qd);
        size_t base_hi = base_lo + (size_t)8 * S_LEN;

        float2 dlo[2], dhi[2], elo[2], ehi[2];
        int2   mlo[2], mhi[2];
        #pragma unroll
        for (int j = 0; j < 2; ++j) {
            dlo[j] = *(const float2*)(dist + base_lo + j * 8);
            dhi[j] = *(const float2*)(dist + base_hi + j * 8);
            elo[j] = *(const float2*)(ener + base_lo + j * 8);
            ehi[j] = *(const float2*)(ener + base_hi + j * 8);
            mlo[j] = *(const int2*)(mask + base_lo + j * 8);
            mhi[j] = *(const int2*)(mask + base_hi + j * 8);
        }

        // ---- S = Q K^T : warp computes m16 x n16 (2 n8-subtiles) ----
        float s[2][4];
        #pragma unroll
        for (int j = 0; j < 2; ++j)
            #pragma unroll
            for (int c = 0; c < 4; ++c) s[j][c] = 0.f;

        #pragma unroll
        for (int kf = 0; kf < 8; ++kf) {
            #pragma unroll
            for (int j = 0; j < 2; ++j) {
                int key = nbase + j * 8 + g;
                uint32_t b0 = f2tf(Ksb[key * KSTR + kf * 8 + qd]);
                uint32_t b1 = f2tf(Ksb[key * KSTR + kf * 8 + qd + 4]);
                mma_tf32(s[j][0], s[j][1], s[j][2], s[j][3],
                         qf[kf][0], qf[kf][1], qf[kf][2], qf[kf][3], b0, b1);
            }
        }

        // ---- apply biases + mask ----
        #pragma unroll
        for (int j = 0; j < 2; ++j) {
            float v00 = s[j][0] + lut(tD, dlo[j].x, inv_step) + lut(tE, elo[j].x, inv_step);
            float v01 = s[j][1] + lut(tD, dlo[j].y, inv_step) + lut(tE, elo[j].y, inv_step);
            float v10 = s[j][2] + lut(tD, dhi[j].x, inv_step) + lut(tE, ehi[j].x, inv_step);
            float v11 = s[j][3] + lut(tD, dhi[j].y, inv_step) + lut(tE, ehi[j].y, inv_step);
            s[j][0] = (mlo[j].x == 0) ? -1e9f : v00;
            s[j][1] = (mlo[j].y == 0) ? -1e9f : v01;
            s[j][2] = (mhi[j].x == 0) ? -1e9f : v10;
            s[j][3] = (mhi[j].y == 0) ? -1e9f : v11;
        }

        // ---- quarter-local online softmax (intra-warp only) ----
        float pl = fmaxf(fmaxf(s[0][0], s[0][1]), fmaxf(s[1][0], s[1][1]));
        float ph = fmaxf(fmaxf(s[0][2], s[0][3]), fmaxf(s[1][2], s[1][3]));
        pl = fmaxf(pl, __shfl_xor_sync(0xffffffffu, pl, 1));
        pl = fmaxf(pl, __shfl_xor_sync(0xffffffffu, pl, 2));
        ph = fmaxf(ph, __shfl_xor_sync(0xffffffffu, ph, 1));
        ph = fmaxf(ph, __shfl_xor_sync(0xffffffffu, ph, 2));

        float nm_lo = fmaxf(m_lo, pl);
        float nm_hi = fmaxf(m_hi, ph);
        float c_lo = __expf(m_lo - nm_lo);
        float c_hi = __expf(m_hi - nm_hi);
        m_lo = nm_lo; m_hi = nm_hi;

        float sl = 0.f, sh = 0.f;
        #pragma unroll
        for (int j = 0; j < 2; ++j) {
            s[j][0] = __expf(s[j][0] - nm_lo); sl += s[j][0];
            s[j][1] = __expf(s[j][1] - nm_lo); sl += s[j][1];
            s[j][2] = __expf(s[j][2] - nm_hi); sh += s[j][2];
            s[j][3] = __expf(s[j][3] - nm_hi); sh += s[j][3];
        }
        sl += __shfl_xor_sync(0xffffffffu, sl, 1);
        sl += __shfl_xor_sync(0xffffffffu, sl, 2);
        sh += __shfl_xor_sync(0xffffffffu, sh, 1);
        sh += __shfl_xor_sync(0xffffffffu, sh, 2);
        l_lo = l_lo * c_lo + sl;
        l_hi = l_hi * c_hi + sh;

        #pragma unroll
        for (int j = 0; j < 8; ++j) {
            o[j][0] *= c_lo; o[j][1] *= c_lo;
            o[j][2] *= c_hi; o[j][3] *= c_hi;
        }

        // ---- O += P V over this quarter's 16 keys (2 k8 fragments) ----
        const int l0 = g * 4 + (qd >> 1);
        const int l1 = l0 + 2;
        const bool odd = (qd & 1);
        #pragma unroll
        for (int kf = 0; kf < 2; ++kf) {
            float v0 = __shfl_sync(0xffffffffu, s[kf][0], l0);
            float v1 = __shfl_sync(0xffffffffu, s[kf][1], l0);
            float v2 = __shfl_sync(0xffffffffu, s[kf][2], l0);
            float v3 = __shfl_sync(0xffffffffu, s[kf][3], l0);
            float w0 = __shfl_sync(0xffffffffu, s[kf][0], l1);
            float w1 = __shfl_sync(0xffffffffu, s[kf][1], l1);
            float w2 = __shfl_sync(0xffffffffu, s[kf][2], l1);
            float w3 = __shfl_sync(0xffffffffu, s[kf][3], l1);
            uint32_t a0 = f2tf(odd ? v1 : v0);
            uint32_t a1 = f2tf(odd ? v3 : v2);
            uint32_t a2 = f2tf(odd ? w1 : w0);
            uint32_t a3 = f2tf(odd ? w3 : w2);
            int vr = nbase + kf * 8 + qd;
            #pragma unroll
            for (int j = 0; j < 8; ++j) {
                uint32_t b0 = f2tf(Vsb[vr * VSTR + j * 8 + g]);
                uint32_t b1 = f2tf(Vsb[(vr + 4) * VSTR + j * 8 + g]);
                mma_tf32(o[j][0], o[j][1], o[j][2], o[j][3], a0, a1, a2, a3, b0, b1);
            }
        }
    }

    // ---- epilogue: max-merge the 4 independent quarter softmaxes ----
    if (qd == 0) {
        Mred[qt * 32 + r_lo] = m_lo;
        Mred[qt * 32 + r_hi] = m_hi;
        Lred[qt * 32 + r_lo] = l_lo;
        Lred[qt * 32 + r_hi] = l_hi;
    }
    __syncthreads();
    float M_lo = fmaxf(fmaxf(Mred[r_lo], Mred[32 + r_lo]),
                       fmaxf(Mred[64 + r_lo], Mred[96 + r_lo]));
    float M_hi = fmaxf(fmaxf(Mred[r_hi], Mred[32 + r_hi]),
                       fmaxf(Mred[64 + r_hi], Mred[96 + r_hi]));
    float sc_lo = __expf(m_lo - M_lo);
    float sc_hi = __expf(m_hi - M_hi);

    // quarters 1..3 dump scaled partial O into dead K/V buffers
    float* pbuf = (qt == 1) ? Kb0 : (qt == 2) ? Kb1 : Vb0;
    if (qt != 0) {
        #pragma unroll
        for (int j = 0; j < 8; ++j) {
            *(float2*)&pbuf[r_lo * KSTR + j * 8 + 2 * qd] =
                make_float2(o[j][0] * sc_lo, o[j][1] * sc_lo);
            *(float2*)&pbuf[r_hi * KSTR + j * 8 + 2 * qd] =
                make_float2(o[j][2] * sc_hi, o[j][3] * sc_hi);
        }
    }
    __syncthreads();
    if (qt == 0) {
        float lt_lo = Lred[r_lo]      * __expf(Mred[r_lo]      - M_lo)
                    + Lred[32 + r_lo] * __expf(Mred[32 + r_lo] - M_lo)
                    + Lred[64 + r_lo] * __expf(Mred[64 + r_lo] - M_lo)
                    + Lred[96 + r_lo] * __expf(Mred[96 + r_lo] - M_lo);
        float lt_hi = Lred[r_hi]      * __expf(Mred[r_hi]      - M_hi)
                    + Lred[32 + r_hi] * __expf(Mred[32 + r_hi] - M_hi)
                    + Lred[64 + r_hi] * __expf(Mred[64 + r_hi] - M_hi)
                    + Lred[96 + r_hi] * __expf(Mred[96 + r_hi] - M_hi);
        float il_lo = 1.0f / lt_lo;
        float il_hi = 1.0f / lt_hi;
        float* og = out + ((size_t)h * S_LEN + q0) * DH;
        #pragma unroll
        for (int j = 0; j < 8; ++j) {
            int cidx = j * 8 + 2 * qd;
            float2 a0 = *(float2*)&Kb0[r_lo * KSTR + cidx];
            float2 b0 = *(float2*)&Kb1[r_lo * KSTR + cidx];
            float2 c0 = *(float2*)&Vb0[r_lo * KSTR + cidx];
            float2 a1 = *(float2*)&Kb0[r_hi * KSTR + cidx];
            float2 b1 = *(float2*)&Kb1[r_hi * KSTR + cidx];
            float2 c1 = *(float2*)&Vb0[r_hi * KSTR + cidx];
            float2 r0 = make_float2((o[j][0] * sc_lo + a0.x + b0.x + c0.x) * il_lo,
                                    (o[j][1] * sc_lo + a0.y + b0.y + c0.y) * il_lo);
            float2 r1 = make_float2((o[j][2] * sc_hi + a1.x + b1.x + c1.x) * il_hi,
                                    (o[j][3] * sc_hi + a1.y + b1.y + c1.y) * il_hi);
            *(float2*)(og + r_lo * DH + cidx) = r0;
            *(float2*)(og + r_hi * DH + cidx) = r1;
        }
    }
}

// ---------------------------------------------------------------------------
// Launch
// ---------------------------------------------------------------------------
extern "C" void kernel_launch(void* const* d_in, const int* in_sizes, int n_in,
                              void* d_out, int out_size)
{
    const float* Q    = (const float*)d_in[0];
    const float* K    = (const float*)d_in[1];
    const float* V    = (const float*)d_in[2];
    const float* dist = (const float*)d_in[3];
    const float* ener = (const float*)d_in[4];
    const int*   mask = (const int*)  d_in[5];
    const float* muD  = (const float*)d_in[6];
    const float* sgD  = (const float*)d_in[7];
    const float* bD   = (const float*)d_in[8];
    const float* muE  = (const float*)d_in[9];
    const float* sgE  = (const float*)d_in[10];
    const float* bE   = (const float*)d_in[11];
    const float* W1   = (const float*)d_in[12];
    const float* b1   = (const float*)d_in[13];
    const float* W2   = (const float*)d_in[14];
    const float* b2   = (const float*)d_in[15];
    float* out = (float*)d_out;

    int KG = in_sizes[6];
    if (KG > 16) KG = 16;

    build_tables_kernel<<<dim3(NTAB / 256, 2), 256>>>(
        muD, sgD, bD, muE, sgE, bE, W1, b1, W2, b2, KG);

    const int SMEM_BYTES = (2 * 64 * KSTR + 2 * 64 * VSTR + 256) * (int)sizeof(float)
                         + 2 * NTAB * (int)sizeof(float2);
    cudaFuncSetAttribute(attn_kernel,
                         cudaFuncAttributeMaxDynamicSharedMemorySize, SMEM_BYTES);

    attn_kernel<<<dim3(S_LEN / BM, HEADS), NTHREADS, SMEM_BYTES>>>(
        Q, K, V, dist, ener, mask, out);
}